// round 7
// baseline (speedup 1.0000x reference)
#include <cuda_runtime.h>
#include <cuda_bf16.h>

#define FDIM 128
#define NN   50000
#define EMAX 800000
#define NBMAX 64

// ---------------- scratch (device globals) ----------------------------------
static __device__ float g_h  [(size_t)NN * FDIM];
static __device__ float g_bn [256];    // [0:128) sum, [128:256) sumsq
static __device__ float g_bnab[256];   // [0:128) scale a, [128:256) shift b
static __device__ float g_w2r[FDIM * FDIM];
static __device__ float g_b2 [FDIM];
static __device__ int   g_cnt[NN];
static __device__ int   g_rowptr[NN + 1];
static __device__ int   g_cursor[NN];
static __device__ int   g_srcs[EMAX];
static __device__ int   g_bsum[NBMAX];
static __device__ int   g_boff[NBMAX + 1];
static __device__ int   g_is64;

// ---------------- edge-index dtype detection --------------------------------
__global__ void k_detect(const void* ei) {
    if (threadIdx.x == 0) {
        const int* p = (const int*)ei;
        g_is64 = (p[1] == 0 && p[3] == 0) ? 1 : 0;
    }
}
__device__ __forceinline__ int edge_val(const void* ei, long long elem) {
    if (g_is64) return reinterpret_cast<const int*>(ei)[2 * elem];
    return reinterpret_cast<const int*>(ei)[elem];
}

// ---------------- zero ------------------------------------------------------
__global__ void k_zero(int n) {
    int i = blockIdx.x * blockDim.x + threadIdx.x;
    if (i < n)   g_cnt[i] = 0;
    if (i < 256) g_bn[i]  = 0.f;
}

// ---------------- CSR build -------------------------------------------------
__global__ void k_hist(const void* __restrict__ ei, int E) {
    int e = blockIdx.x * blockDim.x + threadIdx.x;
    if (e >= E) return;
    atomicAdd(&g_cnt[edge_val(ei, (long long)E + e)], 1);
}

__global__ __launch_bounds__(1024) void k_scan1(int n) {
    __shared__ int warpsum[32];
    int t = threadIdx.x;
    int i = blockIdx.x * 1024 + t;
    int lane = t & 31, wid = t >> 5;
    int v = (i < n) ? g_cnt[i] : 0;
    int x = v;
#pragma unroll
    for (int o = 1; o < 32; o <<= 1) {
        int y = __shfl_up_sync(0xffffffffu, x, o);
        if (lane >= o) x += y;
    }
    if (lane == 31) warpsum[wid] = x;
    __syncthreads();
    if (wid == 0) {
        int s = warpsum[lane];
#pragma unroll
        for (int o = 1; o < 32; o <<= 1) {
            int y = __shfl_up_sync(0xffffffffu, s, o);
            if (lane >= o) s += y;
        }
        warpsum[lane] = s;
    }
    __syncthreads();
    int base = (wid > 0) ? warpsum[wid - 1] : 0;
    int incl = base + x;
    if (i < n) g_rowptr[i] = incl - v;
    if (t == 1023) g_bsum[blockIdx.x] = incl;
}

__global__ void k_scan2(int nb) {
    if (threadIdx.x == 0) {
        int run = 0;
        for (int b = 0; b < nb; b++) { g_boff[b] = run; run += g_bsum[b]; }
        g_boff[nb] = run;
    }
}

__global__ __launch_bounds__(1024) void k_scan3(int n, int nb) {
    int i = blockIdx.x * 1024 + threadIdx.x;
    if (i < n) {
        int v = g_rowptr[i] + g_boff[blockIdx.x];
        g_rowptr[i] = v;
        g_cursor[i] = v;
    }
    if (i == 0) g_rowptr[n] = g_boff[nb];
}

__global__ void k_permute(const void* __restrict__ ei, int E) {
    int e = blockIdx.x * blockDim.x + threadIdx.x;
    if (e >= E) return;
    int sidx = edge_val(ei, e);
    int d    = edge_val(ei, (long long)E + e);
    g_srcs[atomicAdd(&g_cursor[d], 1)] = sidx;
}

// ---------------- bf16 split helpers ----------------------------------------
__device__ __forceinline__ unsigned bpack(__nv_bfloat16 a, __nv_bfloat16 b) {
    __nv_bfloat162 v; v.x = a; v.y = b;
    return *reinterpret_cast<unsigned*>(&v);
}
__device__ __forceinline__ void split2(float x, float y,
                                       unsigned& hi, unsigned& lo) {
    __nv_bfloat16 hx = __float2bfloat16(x);
    __nv_bfloat16 hy = __float2bfloat16(y);
    float rx = x - __bfloat162float(hx);
    float ry = y - __bfloat162float(hy);
    hi = bpack(hx, hy);
    lo = bpack(__float2bfloat16(rx), __float2bfloat16(ry));
}
__device__ __forceinline__ void mma16816(float* c, const unsigned* a,
                                         const unsigned* b) {
    asm volatile(
        "mma.sync.aligned.m16n8k16.row.col.f32.bf16.bf16.f32 "
        "{%0,%1,%2,%3}, {%4,%5,%6,%7}, {%8,%9}, {%0,%1,%2,%3};"
        : "+f"(c[0]), "+f"(c[1]), "+f"(c[2]), "+f"(c[3])
        : "r"(a[0]), "r"(a[1]), "r"(a[2]), "r"(a[3]), "r"(b[0]), "r"(b[1]));
}

// ---------------- fused gather-agg + SAGE GEMM + epilogue --------------------
// Phase 0: 8 warps gather-mean 64 dst rows (CSR) into full-K smem A-tile
//          (bf16 hi/lo, stride 68 => conflict-free fragments).
//          LAYER==2 applies folded BN affine to the mean (deg>0 gated).
// Main:    64x128 C-tile, 8 warps (2x4), 2x4 m16n8k16 per warp, 3-MMA
//          bf16 hi/lo split; K=256 = 4 agg chunks (smem) + 4 root chunks
//          (global, register-prefetched).
// Epilogue: bias + row-L2-norm; LAYER==1: ReLU + fused BN stats -> g_h;
//           LAYER==2: FC head (h2 @ Wfc^T + bfc) -> out[N,8] directly.
#define SSTRIDE 20
#define AGS     68
#define OFF_AGH 0
#define OFF_AGL 4352
#define OFF_ASH 8704
#define OFF_ASL 9984
#define OFF_BSH 11264
#define OFF_BSL 13824
#define OFF_RSQ 16384
#define OFF_CST 16448
#define OFF_WFS 16704
#define OFF_BFS 17728
#define OFF_OT  17736
#define SMEM_U32 18312
#define SMEM_BYTES (SMEM_U32 * 4)

template<int LAYER>
__global__ __launch_bounds__(256, 2)
void k_sage_tc(const float* __restrict__ x,
               const float* __restrict__ Wl, const float* __restrict__ bl,
               const float* __restrict__ Wr,
               const float* __restrict__ Wfc, const float* __restrict__ bfc,
               float* __restrict__ outp, int n) {
    extern __shared__ __align__(16) unsigned dsm[];
    unsigned* Agh = dsm + OFF_AGH;
    unsigned* Agl = dsm + OFF_AGL;
    unsigned* AsH = dsm + OFF_ASH;
    unsigned* AsL = dsm + OFF_ASL;
    unsigned* BsH = dsm + OFF_BSH;
    unsigned* BsL = dsm + OFF_BSL;
    float* rowsq   = (float*)(dsm + OFF_RSQ);
    float* colstat = (float*)(dsm + OFF_CST);
    float* Wfs     = (float*)(dsm + OFF_WFS);
    float* bfs     = (float*)(dsm + OFF_BFS);
    float* outt    = (float*)(dsm + OFF_OT);

    const float* src = (LAYER == 1) ? x : g_h;   // gather + root input

    int t    = threadIdx.x;
    int lane = t & 31;
    int w    = t >> 5;
    int g    = lane >> 2;
    int tig  = lane & 3;
    int wr   = w >> 2;
    int wc   = w & 3;
    int row0 = blockIdx.x * 64;

    if (t < 64) rowsq[t] = 0.f;
    if (LAYER == 1) colstat[t] = 0.f;
    if (LAYER == 2) {
        reinterpret_cast<float4*>(Wfs)[t] = reinterpret_cast<const float4*>(Wfc)[t];
        if (t < 8) bfs[t] = bfc[t];
        if (t < 64)
#pragma unroll
            for (int o = 0; o < 8; o++) outt[t * 9 + o] = 0.f;
    }

    // ---------- phase 0: gather-mean into Agh/Agl ----------
    for (int rr = 0; rr < 8; rr++) {
        int rl = w * 8 + rr;
        int r  = row0 + rl;
        float4 a = make_float4(0.f, 0.f, 0.f, 0.f);
        if (r < n) {
            int beg = g_rowptr[r], end = g_rowptr[r + 1];
            float4 c0 = a, c1 = a, c2 = a, c3 = a;
            for (int i = beg; i < end; i += 32) {
                int idx = (i + lane < end) ? g_srcs[i + lane] : 0;
                int cnt = min(32, end - i);
                int j = 0;
                for (; j + 4 <= cnt; j += 4) {
                    int s0 = __shfl_sync(0xffffffffu, idx, j);
                    int s1 = __shfl_sync(0xffffffffu, idx, j + 1);
                    int s2 = __shfl_sync(0xffffffffu, idx, j + 2);
                    int s3 = __shfl_sync(0xffffffffu, idx, j + 3);
                    float4 v0 = ((const float4*)(src + (size_t)s0 * FDIM))[lane];
                    float4 v1 = ((const float4*)(src + (size_t)s1 * FDIM))[lane];
                    float4 v2 = ((const float4*)(src + (size_t)s2 * FDIM))[lane];
                    float4 v3 = ((const float4*)(src + (size_t)s3 * FDIM))[lane];
                    c0.x += v0.x; c0.y += v0.y; c0.z += v0.z; c0.w += v0.w;
                    c1.x += v1.x; c1.y += v1.y; c1.z += v1.z; c1.w += v1.w;
                    c2.x += v2.x; c2.y += v2.y; c2.z += v2.z; c2.w += v2.w;
                    c3.x += v3.x; c3.y += v3.y; c3.z += v3.z; c3.w += v3.w;
                }
                for (; j < cnt; j++) {
                    int s0 = __shfl_sync(0xffffffffu, idx, j);
                    float4 v0 = ((const float4*)(src + (size_t)s0 * FDIM))[lane];
                    c0.x += v0.x; c0.y += v0.y; c0.z += v0.z; c0.w += v0.w;
                }
            }
            if (end > beg) {
                float inv = 1.0f / (float)(end - beg);
                a.x = (c0.x + c1.x + c2.x + c3.x) * inv;
                a.y = (c0.y + c1.y + c2.y + c3.y) * inv;
                a.z = (c0.z + c1.z + c2.z + c3.z) * inv;
                a.w = (c0.w + c1.w + c2.w + c3.w) * inv;
                if (LAYER == 2) {
                    float4 sa = ((const float4*)g_bnab)[lane];
                    float4 sb = ((const float4*)g_bnab)[32 + lane];
                    a.x = fmaf(a.x, sa.x, sb.x);
                    a.y = fmaf(a.y, sa.y, sb.y);
                    a.z = fmaf(a.z, sa.z, sb.z);
                    a.w = fmaf(a.w, sa.w, sb.w);
                }
            }
        }
        unsigned h0, l0, h1, l1;
        split2(a.x, a.y, h0, l0);
        split2(a.z, a.w, h1, l1);
        Agh[rl * AGS + lane * 2]     = h0;
        Agh[rl * AGS + lane * 2 + 1] = h1;
        Agl[rl * AGS + lane * 2]     = l0;
        Agl[rl * AGS + lane * 2 + 1] = l1;
    }

    // ---------- main loop ----------
    int arow = t >> 2, akv = (t * 2) & 7;
    int brow = t >> 1, bkv = (t * 4) & 7;
    int agrow = row0 + arow;
    bool aok = (agrow < n);

    float acc[2][4][4];
#pragma unroll
    for (int i = 0; i < 2; i++)
#pragma unroll
        for (int j = 0; j < 4; j++)
#pragma unroll
            for (int l = 0; l < 4; l++) acc[i][j][l] = 0.f;

    float4 pa[2], pb[4];
#pragma unroll
    for (int u = 0; u < 4; u++)
        pb[u] = *(const float4*)(Wl + brow * FDIM + (bkv + u) * 4);

#pragma unroll 1
    for (int tt = 0; tt < 8; tt++) {
        __syncthreads();
        if (tt >= 4) {
#pragma unroll
            for (int u = 0; u < 2; u++) {
                unsigned h0, l0, h1, l1;
                split2(pa[u].x, pa[u].y, h0, l0);
                split2(pa[u].z, pa[u].w, h1, l1);
                int c0 = arow * SSTRIDE + (akv + u) * 2;
                AsH[c0] = h0; AsH[c0 + 1] = h1;
                AsL[c0] = l0; AsL[c0 + 1] = l1;
            }
        }
#pragma unroll
        for (int u = 0; u < 4; u++) {
            unsigned h0, l0, h1, l1;
            split2(pb[u].x, pb[u].y, h0, l0);
            split2(pb[u].z, pb[u].w, h1, l1);
            int c0 = brow * SSTRIDE + (bkv + u) * 2;
            BsH[c0] = h0; BsH[c0 + 1] = h1;
            BsL[c0] = l0; BsL[c0 + 1] = l1;
        }
        __syncthreads();

        if (tt < 7) {
            int nt = tt + 1;
            const float* W = (nt >= 4) ? Wr : Wl;
            int kb = (nt & 3) * 32;
#pragma unroll
            for (int u = 0; u < 4; u++)
                pb[u] = *(const float4*)(W + brow * FDIM + kb + (bkv + u) * 4);
            if (nt >= 4) {
#pragma unroll
                for (int u = 0; u < 2; u++) {
                    pa[u] = make_float4(0.f, 0.f, 0.f, 0.f);
                    if (aok)
                        pa[u] = *(const float4*)(
                            src + (size_t)agrow * FDIM + kb + (akv + u) * 4);
                }
            }
        }

        const unsigned* Ah; const unsigned* Al; int astr;
        if (tt < 4) { Ah = Agh + tt * 16; Al = Agl + tt * 16; astr = AGS; }
        else        { Ah = AsH;           Al = AsL;           astr = SSTRIDE; }

#pragma unroll
        for (int kt = 0; kt < 2; kt++) {
            unsigned bh[4][2], bl2[4][2];
#pragma unroll
            for (int ct = 0; ct < 4; ct++) {
                int bro = (wc * 32 + ct * 8 + g) * SSTRIDE + kt * 8;
                bh[ct][0]  = BsH[bro + tig];
                bh[ct][1]  = BsH[bro + tig + 4];
                bl2[ct][0] = BsL[bro + tig];
                bl2[ct][1] = BsL[bro + tig + 4];
            }
#pragma unroll
            for (int rt = 0; rt < 2; rt++) {
                int ar0 = (wr * 32 + rt * 16 + g) * astr + kt * 8;
                int ar1 = ar0 + 8 * astr;
                unsigned ah[4] = {Ah[ar0 + tig], Ah[ar1 + tig],
                                  Ah[ar0 + tig + 4], Ah[ar1 + tig + 4]};
                unsigned al[4] = {Al[ar0 + tig], Al[ar1 + tig],
                                  Al[ar0 + tig + 4], Al[ar1 + tig + 4]};
#pragma unroll
                for (int ct = 0; ct < 4; ct++) {
                    mma16816(acc[rt][ct], ah, bh[ct]);
                    mma16816(acc[rt][ct], ah, bl2[ct]);
                    mma16816(acc[rt][ct], al, bh[ct]);
                }
            }
        }
    }

    // ---------- epilogue ----------
    float bias[4][2];
#pragma unroll
    for (int ct = 0; ct < 4; ct++) {
        int col = wc * 32 + ct * 8 + 2 * tig;
        bias[ct][0] = bl[col];
        bias[ct][1] = bl[col + 1];
    }
#pragma unroll
    for (int rt = 0; rt < 2; rt++)
#pragma unroll
        for (int ct = 0; ct < 4; ct++) {
            acc[rt][ct][0] += bias[ct][0];
            acc[rt][ct][1] += bias[ct][1];
            acc[rt][ct][2] += bias[ct][0];
            acc[rt][ct][3] += bias[ct][1];
        }

#pragma unroll
    for (int rt = 0; rt < 2; rt++)
#pragma unroll
        for (int h = 0; h < 2; h++) {
            float s = 0.f;
#pragma unroll
            for (int ct = 0; ct < 4; ct++) {
                float v0 = acc[rt][ct][2 * h], v1 = acc[rt][ct][2 * h + 1];
                s = fmaf(v0, v0, s);
                s = fmaf(v1, v1, s);
            }
            s += __shfl_xor_sync(0xffffffffu, s, 1);
            s += __shfl_xor_sync(0xffffffffu, s, 2);
            if (tig == 0)
                atomicAdd(&rowsq[wr * 32 + rt * 16 + g + 8 * h], s);
        }
    __syncthreads();

    float cs[4][2], cq[4][2];
#pragma unroll
    for (int ct = 0; ct < 4; ct++) {
        cs[ct][0] = cs[ct][1] = 0.f;
        cq[ct][0] = cq[ct][1] = 0.f;
    }

#pragma unroll
    for (int rt = 0; rt < 2; rt++)
#pragma unroll
        for (int h = 0; h < 2; h++) {
            int rl = wr * 32 + rt * 16 + g + 8 * h;
            int r  = row0 + rl;
            if (r >= n) continue;
            float inv = 1.0f / fmaxf(sqrtf(rowsq[rl]), 1e-12f);
            float so[8];
            if (LAYER == 2)
#pragma unroll
                for (int o = 0; o < 8; o++) so[o] = 0.f;
#pragma unroll
            for (int ct = 0; ct < 4; ct++) {
                float v0 = acc[rt][ct][2 * h] * inv;
                float v1 = acc[rt][ct][2 * h + 1] * inv;
                int col = wc * 32 + ct * 8 + 2 * tig;
                if (LAYER == 1) {
                    v0 = fmaxf(v0, 0.f);
                    v1 = fmaxf(v1, 0.f);
                    cs[ct][0] += v0; cs[ct][1] += v1;
                    cq[ct][0] = fmaf(v0, v0, cq[ct][0]);
                    cq[ct][1] = fmaf(v1, v1, cq[ct][1]);
                    *reinterpret_cast<float2*>(g_h + (size_t)r * FDIM + col) =
                        make_float2(v0, v1);
                } else {
#pragma unroll
                    for (int o = 0; o < 8; o++)
                        so[o] = fmaf(v0, Wfs[o * FDIM + col],
                                fmaf(v1, Wfs[o * FDIM + col + 1], so[o]));
                }
            }
            if (LAYER == 2) {
#pragma unroll
                for (int o = 0; o < 8; o++) {
                    so[o] += __shfl_xor_sync(0xffffffffu, so[o], 1);
                    so[o] += __shfl_xor_sync(0xffffffffu, so[o], 2);
                }
                if (tig == 0)
#pragma unroll
                    for (int o = 0; o < 8; o++)
                        atomicAdd(&outt[rl * 9 + o], so[o]);
            }
        }

    if (LAYER == 1) {
#pragma unroll
        for (int ct = 0; ct < 4; ct++)
#pragma unroll
            for (int j = 0; j < 2; j++) {
#pragma unroll
                for (int o = 4; o < 32; o <<= 1) {
                    cs[ct][j] += __shfl_xor_sync(0xffffffffu, cs[ct][j], o);
                    cq[ct][j] += __shfl_xor_sync(0xffffffffu, cq[ct][j], o);
                }
            }
        if (g == 0) {
#pragma unroll
            for (int ct = 0; ct < 4; ct++) {
                int col = wc * 32 + ct * 8 + 2 * tig;
                atomicAdd(&colstat[col],           cs[ct][0]);
                atomicAdd(&colstat[col + 1],       cs[ct][1]);
                atomicAdd(&colstat[128 + col],     cq[ct][0]);
                atomicAdd(&colstat[128 + col + 1], cq[ct][1]);
            }
        }
        __syncthreads();
        atomicAdd(&g_bn[t], colstat[t]);
    } else {
        __syncthreads();
        if (t < 64) {
            int r = row0 + t;
            if (r < n) {
#pragma unroll
                for (int o = 0; o < 8; o++)
                    outp[(size_t)r * 8 + o] = outt[t * 9 + o] + bfs[o];
            }
        }
    }
}

// ---------------- BN coefficients + root-branch weight folding ---------------
__global__ void k_bncoef(const float* __restrict__ gamma,
                         const float* __restrict__ beta, float invn) {
    int t = threadIdx.x;
    float mu  = g_bn[t] * invn;
    float var = g_bn[128 + t] * invn - mu * mu;
    float a = gamma[t] * rsqrtf(fmaxf(var, 0.f) + 1e-5f);
    g_bnab[t]       = a;
    g_bnab[128 + t] = fmaf(-mu, a, beta[t]);
}

__global__ void k_bnfold(const float* __restrict__ W2r) {
    int i = blockIdx.x * blockDim.x + threadIdx.x;
    if (i >= FDIM * FDIM) return;
    g_w2r[i] = W2r[i] * g_bnab[i & (FDIM - 1)];
}

__global__ void k_bnbias(const float* __restrict__ W2r,
                         const float* __restrict__ b2l) {
    __shared__ float red[128];
    int o = blockIdx.x, t = threadIdx.x;
    red[t] = W2r[o * FDIM + t] * g_bnab[128 + t];
    __syncthreads();
#pragma unroll
    for (int off = 64; off; off >>= 1) {
        if (t < off) red[t] += red[t + off];
        __syncthreads();
    }
    if (t == 0) g_b2[o] = b2l[o] + red[0];
}

// ---------------- launch ------------------------------------------------------
extern "C" void kernel_launch(void* const* d_in, const int* in_sizes, int n_in,
                              void* d_out, int out_size) {
    const float* x   = (const float*)d_in[0];
    const void*  ei  = d_in[1];
    const float* W1l = (const float*)d_in[2];
    const float* b1l = (const float*)d_in[3];
    const float* W1r = (const float*)d_in[4];
    const float* gma = (const float*)d_in[5];
    const float* bta = (const float*)d_in[6];
    const float* W2l = (const float*)d_in[7];
    const float* b2l = (const float*)d_in[8];
    const float* W2r = (const float*)d_in[9];
    const float* Wfc = (const float*)d_in[10];
    const float* bfc = (const float*)d_in[11];
    float* out = (float*)d_out;

    int n  = in_sizes[0] / FDIM;
    int E  = in_sizes[1] / 2;
    int zb = (n + 255) / 256;
    int eb = (E + 255) / 256;
    int gb = (n + 63) / 64;
    int nb = (n + 1023) / 1024;

    cudaFuncSetAttribute(k_sage_tc<1>,
                         cudaFuncAttributeMaxDynamicSharedMemorySize, SMEM_BYTES);
    cudaFuncSetAttribute(k_sage_tc<2>,
                         cudaFuncAttributeMaxDynamicSharedMemorySize, SMEM_BYTES);

    float* w2rp; cudaGetSymbolAddress((void**)&w2rp, g_w2r);
    float* b2p;  cudaGetSymbolAddress((void**)&b2p,  g_b2);

    k_detect<<<1, 32>>>(ei);
    k_zero<<<zb, 256>>>(n);
    k_hist<<<eb, 256>>>(ei, E);
    k_scan1<<<nb, 1024>>>(n);
    k_scan2<<<1, 32>>>(nb);
    k_scan3<<<nb, 1024>>>(n, nb);
    k_permute<<<eb, 256>>>(ei, E);
    k_sage_tc<1><<<gb, 256, SMEM_BYTES>>>(x, W1l, b1l, W1r, Wfc, bfc, out, n);
    k_bncoef<<<1, 128>>>(gma, bta, 1.0f / (float)n);
    k_bnfold<<<(FDIM * FDIM + 255) / 256, 256>>>(W2r);
    k_bnbias<<<FDIM, 128>>>(W2r, b2l);
    k_sage_tc<2><<<gb, 256, SMEM_BYTES>>>(x, W2l, b2p, w2rp, Wfc, bfc, out, n);
}

// round 8
// speedup vs baseline: 1.0342x; 1.0342x over previous
#include <cuda_runtime.h>
#include <cuda_bf16.h>

#define FDIM 128
#define NN   50000
#define EMAX 800000
#define NBMAX 64

// ---------------- scratch (device globals) ----------------------------------
static __device__ float g_agg[(size_t)NN * FDIM];
static __device__ float g_h  [(size_t)NN * FDIM];
static __device__ float g_bn [256];    // [0:128) sum, [128:256) sumsq
static __device__ float g_bnab[256];   // [0:128) scale a, [128:256) shift b
static __device__ float g_w2r[FDIM * FDIM];
static __device__ float g_b2 [FDIM];
static __device__ int   g_cnt[NN];
static __device__ int   g_rowptr[NN + 1];
static __device__ int   g_cursor[NN];
static __device__ int   g_srcs[EMAX];
static __device__ int   g_bsum[NBMAX];
static __device__ int   g_boff[NBMAX + 1];
static __device__ int   g_is64;

// ---------------- edge-index dtype detection --------------------------------
__global__ void k_detect(const void* ei) {
    if (threadIdx.x == 0) {
        const int* p = (const int*)ei;
        g_is64 = (p[1] == 0 && p[3] == 0) ? 1 : 0;
    }
}
__device__ __forceinline__ int edge_val(const void* ei, long long elem) {
    if (g_is64) return reinterpret_cast<const int*>(ei)[2 * elem];
    return reinterpret_cast<const int*>(ei)[elem];
}

// ---------------- zero ------------------------------------------------------
__global__ void k_zero(int n) {
    int i = blockIdx.x * blockDim.x + threadIdx.x;
    if (i < n)   g_cnt[i] = 0;
    if (i < 256) g_bn[i]  = 0.f;
}

// ---------------- CSR build -------------------------------------------------
__global__ void k_hist(const void* __restrict__ ei, int E) {
    int e = blockIdx.x * blockDim.x + threadIdx.x;
    if (e >= E) return;
    atomicAdd(&g_cnt[edge_val(ei, (long long)E + e)], 1);
}

__global__ __launch_bounds__(1024) void k_scan1(int n) {
    __shared__ int warpsum[32];
    int t = threadIdx.x;
    int i = blockIdx.x * 1024 + t;
    int lane = t & 31, wid = t >> 5;
    int v = (i < n) ? g_cnt[i] : 0;
    int x = v;
#pragma unroll
    for (int o = 1; o < 32; o <<= 1) {
        int y = __shfl_up_sync(0xffffffffu, x, o);
        if (lane >= o) x += y;
    }
    if (lane == 31) warpsum[wid] = x;
    __syncthreads();
    if (wid == 0) {
        int s = warpsum[lane];
#pragma unroll
        for (int o = 1; o < 32; o <<= 1) {
            int y = __shfl_up_sync(0xffffffffu, s, o);
            if (lane >= o) s += y;
        }
        warpsum[lane] = s;
    }
    __syncthreads();
    int base = (wid > 0) ? warpsum[wid - 1] : 0;
    int incl = base + x;
    if (i < n) g_rowptr[i] = incl - v;
    if (t == 1023) g_bsum[blockIdx.x] = incl;
}

__global__ void k_scan2(int nb) {
    if (threadIdx.x == 0) {
        int run = 0;
        for (int b = 0; b < nb; b++) { g_boff[b] = run; run += g_bsum[b]; }
        g_boff[nb] = run;
    }
}

__global__ __launch_bounds__(1024) void k_scan3(int n, int nb) {
    int i = blockIdx.x * 1024 + threadIdx.x;
    if (i < n) {
        int v = g_rowptr[i] + g_boff[blockIdx.x];
        g_rowptr[i] = v;
        g_cursor[i] = v;
    }
    if (i == 0) g_rowptr[n] = g_boff[nb];
}

__global__ void k_permute(const void* __restrict__ ei, int E) {
    int e = blockIdx.x * blockDim.x + threadIdx.x;
    if (e >= E) return;
    int sidx = edge_val(ei, e);
    int d    = edge_val(ei, (long long)E + e);
    g_srcs[atomicAdd(&g_cursor[d], 1)] = sidx;
}

// ---------------- aggregation: warp per dst row, gather-sum + mean ----------
// BN=1: output = a * mean + b  (per column, only when deg>0), exact BN fold.
template<int BN>
__global__ void k_agg(const float* __restrict__ xin, int n) {
    int w    = (blockIdx.x * blockDim.x + threadIdx.x) >> 5;
    int lane = threadIdx.x & 31;
    if (w >= n) return;
    const float* buf = (BN == 0) ? xin : g_h;

    int beg = g_rowptr[w], end = g_rowptr[w + 1];
    float4 acc0 = make_float4(0.f, 0.f, 0.f, 0.f);
    float4 acc1 = acc0, acc2 = acc0, acc3 = acc0;

    for (int i = beg; i < end; i += 32) {
        int idx = (i + lane < end) ? g_srcs[i + lane] : 0;
        int cnt = min(32, end - i);
        int j = 0;
        for (; j + 4 <= cnt; j += 4) {
            int s0 = __shfl_sync(0xffffffffu, idx, j);
            int s1 = __shfl_sync(0xffffffffu, idx, j + 1);
            int s2 = __shfl_sync(0xffffffffu, idx, j + 2);
            int s3 = __shfl_sync(0xffffffffu, idx, j + 3);
            float4 v0 = reinterpret_cast<const float4*>(buf + (size_t)s0 * FDIM)[lane];
            float4 v1 = reinterpret_cast<const float4*>(buf + (size_t)s1 * FDIM)[lane];
            float4 v2 = reinterpret_cast<const float4*>(buf + (size_t)s2 * FDIM)[lane];
            float4 v3 = reinterpret_cast<const float4*>(buf + (size_t)s3 * FDIM)[lane];
            acc0.x += v0.x; acc0.y += v0.y; acc0.z += v0.z; acc0.w += v0.w;
            acc1.x += v1.x; acc1.y += v1.y; acc1.z += v1.z; acc1.w += v1.w;
            acc2.x += v2.x; acc2.y += v2.y; acc2.z += v2.z; acc2.w += v2.w;
            acc3.x += v3.x; acc3.y += v3.y; acc3.z += v3.z; acc3.w += v3.w;
        }
        for (; j < cnt; j++) {
            int s0 = __shfl_sync(0xffffffffu, idx, j);
            float4 v0 = reinterpret_cast<const float4*>(buf + (size_t)s0 * FDIM)[lane];
            acc0.x += v0.x; acc0.y += v0.y; acc0.z += v0.z; acc0.w += v0.w;
        }
    }
    float4 o = make_float4(0.f, 0.f, 0.f, 0.f);
    if (end > beg) {
        float inv = 1.0f / (float)(end - beg);
        o.x = (acc0.x + acc1.x + acc2.x + acc3.x) * inv;
        o.y = (acc0.y + acc1.y + acc2.y + acc3.y) * inv;
        o.z = (acc0.z + acc1.z + acc2.z + acc3.z) * inv;
        o.w = (acc0.w + acc1.w + acc2.w + acc3.w) * inv;
        if (BN == 1) {
            float4 a = reinterpret_cast<const float4*>(g_bnab)[lane];
            float4 b = reinterpret_cast<const float4*>(g_bnab)[32 + lane];
            o.x = fmaf(o.x, a.x, b.x);
            o.y = fmaf(o.y, a.y, b.y);
            o.z = fmaf(o.z, a.z, b.z);
            o.w = fmaf(o.w, a.w, b.w);
        }
    }
    reinterpret_cast<float4*>(g_agg + (size_t)w * FDIM)[lane] = o;
}

// ---------------- bf16 split helpers ----------------------------------------
__device__ __forceinline__ unsigned bpack(__nv_bfloat16 a, __nv_bfloat16 b) {
    __nv_bfloat162 v; v.x = a; v.y = b;
    return *reinterpret_cast<unsigned*>(&v);
}
__device__ __forceinline__ void split2(float x, float y,
                                       unsigned& hi, unsigned& lo) {
    __nv_bfloat16 hx = __float2bfloat16(x);
    __nv_bfloat16 hy = __float2bfloat16(y);
    float rx = x - __bfloat162float(hx);
    float ry = y - __bfloat162float(hy);
    hi = bpack(hx, hy);
    lo = bpack(__float2bfloat16(rx), __float2bfloat16(ry));
}
__device__ __forceinline__ void mma16816(float* c, const unsigned* a,
                                         const unsigned* b) {
    asm volatile(
        "mma.sync.aligned.m16n8k16.row.col.f32.bf16.bf16.f32 "
        "{%0,%1,%2,%3}, {%4,%5,%6,%7}, {%8,%9}, {%0,%1,%2,%3};"
        : "+f"(c[0]), "+f"(c[1]), "+f"(c[2]), "+f"(c[3])
        : "r"(a[0]), "r"(a[1]), "r"(a[2]), "r"(a[3]), "r"(b[0]), "r"(b[1]));
}

// ---------------- tensor-core SAGE linear + bias + L2-norm -------------------
// C[64x128] per block, 256 threads (8 warps: 2x4), warp tile 32x32 = 2x4
// m16n8k16 tiles, bf16 hi/lo split (3 MMAs). K=256 in 8 chunks, register
// prefetch. LAYER==1: ReLU + fused BN stats -> g_h.
// LAYER==2: fused FC head (h2 @ Wfc^T + bfc) -> out[N,8] directly.
#define SSTRIDE 20
template<int LAYER>
__global__ __launch_bounds__(256)
void k_sage_tc(const float* __restrict__ xin,
               const float* __restrict__ Wl, const float* __restrict__ bl,
               const float* __restrict__ Wr,
               const float* __restrict__ Wfc, const float* __restrict__ bfc,
               float* __restrict__ outp, int n) {
    __shared__ unsigned As_hi[64 * SSTRIDE], As_lo[64 * SSTRIDE];
    __shared__ unsigned Bs_hi[128 * SSTRIDE], Bs_lo[128 * SSTRIDE];
    __shared__ float rowsq[64];
    __shared__ float colstat[256];
    __shared__ __align__(16) float Wfs[8 * FDIM];
    __shared__ float bfs[8];
    __shared__ float outt[64 * 9];

    const float* A2 = (LAYER == 1) ? xin : g_h;

    int t    = threadIdx.x;
    int lane = t & 31;
    int w    = t >> 5;
    int g    = lane >> 2;
    int tig  = lane & 3;
    int wr   = w >> 2;
    int wc   = w & 3;
    int row0 = blockIdx.x * 64;

    int arow = t >> 2, akv = (t * 2) & 7;
    int brow = t >> 1, bkv = (t * 4) & 7;
    int agrow = row0 + arow;
    bool aok = (agrow < n);

    if (t < 64) rowsq[t] = 0.f;
    if (LAYER == 1) colstat[t] = 0.f;
    if (LAYER == 2) {
        reinterpret_cast<float4*>(Wfs)[t] = reinterpret_cast<const float4*>(Wfc)[t];
        if (t < 8) bfs[t] = bfc[t];
        if (t < 64)
#pragma unroll
            for (int o = 0; o < 8; o++) outt[t * 9 + o] = 0.f;
    }

    float acc[2][4][4];
#pragma unroll
    for (int i = 0; i < 2; i++)
#pragma unroll
        for (int j = 0; j < 4; j++)
#pragma unroll
            for (int l = 0; l < 4; l++) acc[i][j][l] = 0.f;

    float4 pa[2], pb[4];
    {
#pragma unroll
        for (int u = 0; u < 2; u++) {
            pa[u] = make_float4(0.f, 0.f, 0.f, 0.f);
            if (aok)
                pa[u] = *reinterpret_cast<const float4*>(
                    g_agg + (size_t)agrow * FDIM + (akv + u) * 4);
        }
#pragma unroll
        for (int u = 0; u < 4; u++)
            pb[u] = *reinterpret_cast<const float4*>(
                Wl + brow * FDIM + (bkv + u) * 4);
    }

#pragma unroll 1
    for (int tt = 0; tt < 8; tt++) {
        __syncthreads();
#pragma unroll
        for (int u = 0; u < 2; u++) {
            unsigned h0, l0, h1, l1;
            split2(pa[u].x, pa[u].y, h0, l0);
            split2(pa[u].z, pa[u].w, h1, l1);
            int c0 = arow * SSTRIDE + (akv + u) * 2;
            As_hi[c0] = h0; As_hi[c0 + 1] = h1;
            As_lo[c0] = l0; As_lo[c0 + 1] = l1;
        }
#pragma unroll
        for (int u = 0; u < 4; u++) {
            unsigned h0, l0, h1, l1;
            split2(pb[u].x, pb[u].y, h0, l0);
            split2(pb[u].z, pb[u].w, h1, l1);
            int c0 = brow * SSTRIDE + (bkv + u) * 2;
            Bs_hi[c0] = h0; Bs_hi[c0 + 1] = h1;
            Bs_lo[c0] = l0; Bs_lo[c0 + 1] = l1;
        }
        __syncthreads();

        if (tt < 7) {
            int nt = tt + 1;
            const float* A = (nt & 4) ? A2 : g_agg;
            const float* W = (nt & 4) ? Wr : Wl;
            int kbase = (nt & 3) * 32;
#pragma unroll
            for (int u = 0; u < 2; u++) {
                pa[u] = make_float4(0.f, 0.f, 0.f, 0.f);
                if (aok)
                    pa[u] = *reinterpret_cast<const float4*>(
                        A + (size_t)agrow * FDIM + kbase + (akv + u) * 4);
            }
#pragma unroll
            for (int u = 0; u < 4; u++)
                pb[u] = *reinterpret_cast<const float4*>(
                    W + brow * FDIM + kbase + (bkv + u) * 4);
        }

#pragma unroll
        for (int kt = 0; kt < 2; kt++) {
            unsigned bh[4][2], bl2[4][2];
#pragma unroll
            for (int ct = 0; ct < 4; ct++) {
                int bro = (wc * 32 + ct * 8 + g) * SSTRIDE + kt * 8;
                bh[ct][0]  = Bs_hi[bro + tig];
                bh[ct][1]  = Bs_hi[bro + tig + 4];
                bl2[ct][0] = Bs_lo[bro + tig];
                bl2[ct][1] = Bs_lo[bro + tig + 4];
            }
#pragma unroll
            for (int rt = 0; rt < 2; rt++) {
                int ar0 = (wr * 32 + rt * 16 + g) * SSTRIDE + kt * 8;
                int ar1 = ar0 + 8 * SSTRIDE;
                unsigned ah[4] = {As_hi[ar0 + tig], As_hi[ar1 + tig],
                                  As_hi[ar0 + tig + 4], As_hi[ar1 + tig + 4]};
                unsigned al[4] = {As_lo[ar0 + tig], As_lo[ar1 + tig],
                                  As_lo[ar0 + tig + 4], As_lo[ar1 + tig + 4]};
#pragma unroll
                for (int ct = 0; ct < 4; ct++) {
                    mma16816(acc[rt][ct], ah, bh[ct]);
                    mma16816(acc[rt][ct], ah, bl2[ct]);
                    mma16816(acc[rt][ct], al, bh[ct]);
                }
            }
        }
    }

    // ---------- epilogue ----------
    float bias[4][2];
#pragma unroll
    for (int ct = 0; ct < 4; ct++) {
        int col = wc * 32 + ct * 8 + 2 * tig;
        bias[ct][0] = bl[col];
        bias[ct][1] = bl[col + 1];
    }
#pragma unroll
    for (int rt = 0; rt < 2; rt++)
#pragma unroll
        for (int ct = 0; ct < 4; ct++) {
            acc[rt][ct][0] += bias[ct][0];
            acc[rt][ct][1] += bias[ct][1];
            acc[rt][ct][2] += bias[ct][0];
            acc[rt][ct][3] += bias[ct][1];
        }

#pragma unroll
    for (int rt = 0; rt < 2; rt++)
#pragma unroll
        for (int h = 0; h < 2; h++) {
            float s = 0.f;
#pragma unroll
            for (int ct = 0; ct < 4; ct++) {
                float v0 = acc[rt][ct][2 * h], v1 = acc[rt][ct][2 * h + 1];
                s = fmaf(v0, v0, s);
                s = fmaf(v1, v1, s);
            }
            s += __shfl_xor_sync(0xffffffffu, s, 1);
            s += __shfl_xor_sync(0xffffffffu, s, 2);
            if (tig == 0)
                atomicAdd(&rowsq[wr * 32 + rt * 16 + g + 8 * h], s);
        }
    __syncthreads();

    float cs[4][2], cq[4][2];
#pragma unroll
    for (int ct = 0; ct < 4; ct++) {
        cs[ct][0] = cs[ct][1] = 0.f;
        cq[ct][0] = cq[ct][1] = 0.f;
    }

#pragma unroll
    for (int rt = 0; rt < 2; rt++)
#pragma unroll
        for (int h = 0; h < 2; h++) {
            int rl = wr * 32 + rt * 16 + g + 8 * h;
            int r  = row0 + rl;
            if (r >= n) continue;
            float inv = 1.0f / fmaxf(sqrtf(rowsq[rl]), 1e-12f);
            float so[8];
            if (LAYER == 2)
#pragma unroll
                for (int o = 0; o < 8; o++) so[o] = 0.f;
#pragma unroll
            for (int ct = 0; ct < 4; ct++) {
                float v0 = acc[rt][ct][2 * h] * inv;
                float v1 = acc[rt][ct][2 * h + 1] * inv;
                int col = wc * 32 + ct * 8 + 2 * tig;
                if (LAYER == 1) {
                    v0 = fmaxf(v0, 0.f);
                    v1 = fmaxf(v1, 0.f);
                    cs[ct][0] += v0; cs[ct][1] += v1;
                    cq[ct][0] = fmaf(v0, v0, cq[ct][0]);
                    cq[ct][1] = fmaf(v1, v1, cq[ct][1]);
                    *reinterpret_cast<float2*>(g_h + (size_t)r * FDIM + col) =
                        make_float2(v0, v1);
                } else {
#pragma unroll
                    for (int o = 0; o < 8; o++)
                        so[o] = fmaf(v0, Wfs[o * FDIM + col],
                                fmaf(v1, Wfs[o * FDIM + col + 1], so[o]));
                }
            }
            if (LAYER == 2) {
#pragma unroll
                for (int o = 0; o < 8; o++) {
                    so[o] += __shfl_xor_sync(0xffffffffu, so[o], 1);
                    so[o] += __shfl_xor_sync(0xffffffffu, so[o], 2);
                }
                if (tig == 0)
#pragma unroll
                    for (int o = 0; o < 8; o++)
                        atomicAdd(&outt[rl * 9 + o], so[o]);
            }
        }

    if (LAYER == 1) {
#pragma unroll
        for (int ct = 0; ct < 4; ct++)
#pragma unroll
            for (int j = 0; j < 2; j++) {
#pragma unroll
                for (int o = 4; o < 32; o <<= 1) {
                    cs[ct][j] += __shfl_xor_sync(0xffffffffu, cs[ct][j], o);
                    cq[ct][j] += __shfl_xor_sync(0xffffffffu, cq[ct][j], o);
                }
            }
        if (g == 0) {
#pragma unroll
            for (int ct = 0; ct < 4; ct++) {
                int col = wc * 32 + ct * 8 + 2 * tig;
                atomicAdd(&colstat[col],           cs[ct][0]);
                atomicAdd(&colstat[col + 1],       cs[ct][1]);
                atomicAdd(&colstat[128 + col],     cq[ct][0]);
                atomicAdd(&colstat[128 + col + 1], cq[ct][1]);
            }
        }
        __syncthreads();
        atomicAdd(&g_bn[t], colstat[t]);
    } else {
        __syncthreads();
        if (t < 64) {
            int r = row0 + t;
            if (r < n) {
#pragma unroll
                for (int o = 0; o < 8; o++)
                    outp[(size_t)r * 8 + o] = outt[t * 9 + o] + bfs[o];
            }
        }
    }
}

// ---------------- BN coefficients + root-branch weight folding ---------------
__global__ void k_bncoef(const float* __restrict__ gamma,
                         const float* __restrict__ beta, float invn) {
    int t = threadIdx.x;
    float mu  = g_bn[t] * invn;
    float var = g_bn[128 + t] * invn - mu * mu;
    float a = gamma[t] * rsqrtf(fmaxf(var, 0.f) + 1e-5f);
    g_bnab[t]       = a;
    g_bnab[128 + t] = fmaf(-mu, a, beta[t]);
}

__global__ void k_bnfold(const float* __restrict__ W2r) {
    int i = blockIdx.x * blockDim.x + threadIdx.x;
    if (i >= FDIM * FDIM) return;
    g_w2r[i] = W2r[i] * g_bnab[i & (FDIM - 1)];
}

__global__ void k_bnbias(const float* __restrict__ W2r,
                         const float* __restrict__ b2l) {
    __shared__ float red[128];
    int o = blockIdx.x, t = threadIdx.x;
    red[t] = W2r[o * FDIM + t] * g_bnab[128 + t];
    __syncthreads();
#pragma unroll
    for (int off = 64; off; off >>= 1) {
        if (t < off) red[t] += red[t + off];
        __syncthreads();
    }
    if (t == 0) g_b2[o] = b2l[o] + red[0];
}

// ---------------- launch ------------------------------------------------------
extern "C" void kernel_launch(void* const* d_in, const int* in_sizes, int n_in,
                              void* d_out, int out_size) {
    const float* x   = (const float*)d_in[0];
    const void*  ei  = d_in[1];
    const float* W1l = (const float*)d_in[2];
    const float* b1l = (const float*)d_in[3];
    const float* W1r = (const float*)d_in[4];
    const float* gma = (const float*)d_in[5];
    const float* bta = (const float*)d_in[6];
    const float* W2l = (const float*)d_in[7];
    const float* b2l = (const float*)d_in[8];
    const float* W2r = (const float*)d_in[9];
    const float* Wfc = (const float*)d_in[10];
    const float* bfc = (const float*)d_in[11];
    float* out = (float*)d_out;

    int n  = in_sizes[0] / FDIM;
    int E  = in_sizes[1] / 2;
    int zb = (n + 255) / 256;
    int eb = (E + 255) / 256;
    int gb = (n + 63) / 64;
    int ab = (n * 32 + 255) / 256;
    int nb = (n + 1023) / 1024;

    float* w2rp; cudaGetSymbolAddress((void**)&w2rp, g_w2r);
    float* b2p;  cudaGetSymbolAddress((void**)&b2p,  g_b2);

    k_detect<<<1, 32>>>(ei);
    k_zero<<<zb, 256>>>(n);
    k_hist<<<eb, 256>>>(ei, E);
    k_scan1<<<nb, 1024>>>(n);
    k_scan2<<<1, 32>>>(nb);
    k_scan3<<<nb, 1024>>>(n, nb);
    k_permute<<<eb, 256>>>(ei, E);
    k_agg<0><<<ab, 256>>>(x, n);
    k_sage_tc<1><<<gb, 256>>>(x, W1l, b1l, W1r, Wfc, bfc, out, n);
    k_bncoef<<<1, 128>>>(gma, bta, 1.0f / (float)n);
    k_bnfold<<<(FDIM * FDIM + 255) / 256, 256>>>(W2r);
    k_bnbias<<<FDIM, 128>>>(W2r, b2l);
    k_agg<1><<<ab, 256>>>(x, n);
    k_sage_tc<2><<<gb, 256>>>(x, W2l, b2p, w2rp, Wfc, bfc, out, n);
}

// round 9
// speedup vs baseline: 1.0671x; 1.0318x over previous
#include <cuda_runtime.h>
#include <cuda_bf16.h>
#include <cuda_fp16.h>

#define FDIM 128
#define NN   50000
#define EMAX 800000
#define NBMAX 64

// ---------------- scratch (device globals) ----------------------------------
static __device__ float  g_agg[(size_t)NN * FDIM];
static __device__ float  g_h  [(size_t)NN * FDIM];
static __device__ __half g_xh [(size_t)NN * FDIM];
static __device__ __half g_hh [(size_t)NN * FDIM];
static __device__ float  g_bn [256];    // [0:128) sum, [128:256) sumsq
static __device__ float  g_bnab[256];   // [0:128) scale a, [128:256) shift b
static __device__ float  g_w2r[FDIM * FDIM];
static __device__ float  g_b2 [FDIM];
static __device__ int    g_cnt[NN];
static __device__ int    g_rowptr[NN + 1];
static __device__ int    g_cursor[NN];
static __device__ int    g_srcs[EMAX];
static __device__ int    g_bsum[NBMAX];
static __device__ int    g_bflag[NBMAX];

// ---------------- init: zero histogram / bn / scan flags ---------------------
__global__ void k_init(int n) {
    int i = blockIdx.x * blockDim.x + threadIdx.x;
    if (i < n)   g_cnt[i] = 0;
    if (i < 256) g_bn[i]  = 0.f;
    if (i < 64)  g_bflag[i] = 0;
}

// ---------------- CSR build (local int64 detection) --------------------------
__global__ void k_hist(const void* __restrict__ ei, int E) {
    const int* p = (const int*)ei;
    bool is64 = (p[1] == 0 && p[3] == 0);
    int e = blockIdx.x * blockDim.x + threadIdx.x;
    if (e >= E) return;
    int d = is64 ? p[2 * (E + e)] : p[E + e];
    atomicAdd(&g_cnt[d], 1);
}

// single-pass scan: block scan + decoupled lookback (all blocks resident)
__global__ __launch_bounds__(1024) void k_scanall(int n, int nb) {
    __shared__ int warpsum[32];
    __shared__ int s_boff;
    int t = threadIdx.x;
    int bid = blockIdx.x;
    int i = bid * 1024 + t;
    int lane = t & 31, wid = t >> 5;

    int v = (i < n) ? g_cnt[i] : 0;
    int x = v;
#pragma unroll
    for (int o = 1; o < 32; o <<= 1) {
        int y = __shfl_up_sync(0xffffffffu, x, o);
        if (lane >= o) x += y;
    }
    if (lane == 31) warpsum[wid] = x;
    __syncthreads();
    if (wid == 0) {
        int s = warpsum[lane];
#pragma unroll
        for (int o = 1; o < 32; o <<= 1) {
            int y = __shfl_up_sync(0xffffffffu, s, o);
            if (lane >= o) s += y;
        }
        warpsum[lane] = s;
    }
    __syncthreads();
    int base = (wid > 0) ? warpsum[wid - 1] : 0;
    int incl = base + x;
    int total = warpsum[31];

    if (t == 0) {
        g_bsum[bid] = total;
        __threadfence();
        atomicExch(&g_bflag[bid], 1);
        s_boff = 0;
    }
    __syncthreads();
    if (t < bid) {
        while (atomicAdd(&g_bflag[t], 0) == 0) {}
        atomicAdd(&s_boff, *((volatile int*)&g_bsum[t]));
    }
    __syncthreads();
    int boff = s_boff;

    if (i < n) {
        int r = boff + incl - v;
        g_rowptr[i] = r;
        g_cursor[i] = r;
    }
    if (bid == nb - 1 && t == 1023) g_rowptr[n] = boff + incl;
}

__global__ void k_permute(const void* __restrict__ ei, int E) {
    const int* p = (const int*)ei;
    bool is64 = (p[1] == 0 && p[3] == 0);
    int e = blockIdx.x * blockDim.x + threadIdx.x;
    if (e >= E) return;
    int sidx = is64 ? p[2 * e]       : p[e];
    int d    = is64 ? p[2 * (E + e)] : p[E + e];
    g_srcs[atomicAdd(&g_cursor[d], 1)] = sidx;
}

// ---------------- fp16 mirror of x -------------------------------------------
__global__ void k_cvtx(const float* __restrict__ x, int n4) {
    int i = blockIdx.x * blockDim.x + threadIdx.x;
    if (i >= n4) return;
    float4 v = reinterpret_cast<const float4*>(x)[i];
    __half2 h0 = __floats2half2_rn(v.x, v.y);
    __half2 h1 = __floats2half2_rn(v.z, v.w);
    uint2 u;
    u.x = *reinterpret_cast<unsigned*>(&h0);
    u.y = *reinterpret_cast<unsigned*>(&h1);
    reinterpret_cast<uint2*>(g_xh)[i] = u;
}

// ---------------- aggregation: warp per dst row, fp16 gather, fp32 accum ----
// BN=1: output = a * mean + b  (per column, only when deg>0), exact BN fold.
template<int BN>
__global__ void k_agg(int n) {
    int w    = (blockIdx.x * blockDim.x + threadIdx.x) >> 5;
    int lane = threadIdx.x & 31;
    if (w >= n) return;
    const __half* buf = (BN == 0) ? g_xh : g_hh;

    int beg = g_rowptr[w], end = g_rowptr[w + 1];
    float4 acc0 = make_float4(0.f, 0.f, 0.f, 0.f);
    float4 acc1 = acc0, acc2 = acc0, acc3 = acc0;

#define GATHER(sv, accv) do {                                                 \
        uint2 raw = reinterpret_cast<const uint2*>(                           \
            buf + (size_t)(sv) * FDIM)[lane];                                 \
        __half2 ha = *reinterpret_cast<__half2*>(&raw.x);                     \
        __half2 hb = *reinterpret_cast<__half2*>(&raw.y);                     \
        float2 f0 = __half22float2(ha);                                       \
        float2 f1 = __half22float2(hb);                                       \
        accv.x += f0.x; accv.y += f0.y; accv.z += f1.x; accv.w += f1.y;       \
    } while (0)

    for (int i = beg; i < end; i += 32) {
        int idx = (i + lane < end) ? g_srcs[i + lane] : 0;
        int cnt = min(32, end - i);
        int j = 0;
        for (; j + 4 <= cnt; j += 4) {
            int s0 = __shfl_sync(0xffffffffu, idx, j);
            int s1 = __shfl_sync(0xffffffffu, idx, j + 1);
            int s2 = __shfl_sync(0xffffffffu, idx, j + 2);
            int s3 = __shfl_sync(0xffffffffu, idx, j + 3);
            GATHER(s0, acc0); GATHER(s1, acc1);
            GATHER(s2, acc2); GATHER(s3, acc3);
        }
        for (; j < cnt; j++) {
            int s0 = __shfl_sync(0xffffffffu, idx, j);
            GATHER(s0, acc0);
        }
    }
#undef GATHER

    float4 o = make_float4(0.f, 0.f, 0.f, 0.f);
    if (end > beg) {
        float inv = 1.0f / (float)(end - beg);
        o.x = (acc0.x + acc1.x + acc2.x + acc3.x) * inv;
        o.y = (acc0.y + acc1.y + acc2.y + acc3.y) * inv;
        o.z = (acc0.z + acc1.z + acc2.z + acc3.z) * inv;
        o.w = (acc0.w + acc1.w + acc2.w + acc3.w) * inv;
        if (BN == 1) {
            float4 a = reinterpret_cast<const float4*>(g_bnab)[lane];
            float4 b = reinterpret_cast<const float4*>(g_bnab)[32 + lane];
            o.x = fmaf(o.x, a.x, b.x);
            o.y = fmaf(o.y, a.y, b.y);
            o.z = fmaf(o.z, a.z, b.z);
            o.w = fmaf(o.w, a.w, b.w);
        }
    }
    reinterpret_cast<float4*>(g_agg + (size_t)w * FDIM)[lane] = o;
}

// ---------------- bf16 split helpers ----------------------------------------
__device__ __forceinline__ unsigned bpack(__nv_bfloat16 a, __nv_bfloat16 b) {
    __nv_bfloat162 v; v.x = a; v.y = b;
    return *reinterpret_cast<unsigned*>(&v);
}
__device__ __forceinline__ void split2(float x, float y,
                                       unsigned& hi, unsigned& lo) {
    __nv_bfloat16 hx = __float2bfloat16(x);
    __nv_bfloat16 hy = __float2bfloat16(y);
    float rx = x - __bfloat162float(hx);
    float ry = y - __bfloat162float(hy);
    hi = bpack(hx, hy);
    lo = bpack(__float2bfloat16(rx), __float2bfloat16(ry));
}
__device__ __forceinline__ void mma16816(float* c, const unsigned* a,
                                         const unsigned* b) {
    asm volatile(
        "mma.sync.aligned.m16n8k16.row.col.f32.bf16.bf16.f32 "
        "{%0,%1,%2,%3}, {%4,%5,%6,%7}, {%8,%9}, {%0,%1,%2,%3};"
        : "+f"(c[0]), "+f"(c[1]), "+f"(c[2]), "+f"(c[3])
        : "r"(a[0]), "r"(a[1]), "r"(a[2]), "r"(a[3]), "r"(b[0]), "r"(b[1]));
}

// ---------------- tensor-core SAGE linear + bias + L2-norm -------------------
// C[64x128] per block, 256 threads (8 warps: 2x4), warp tile 32x32 = 2x4
// m16n8k16 tiles, bf16 hi/lo split (3 MMAs). K=256 in 8 chunks, register
// prefetch. LAYER==1: ReLU + fused BN stats -> g_h (fp32) + g_hh (fp16).
// LAYER==2: fused FC head (h2 @ Wfc^T + bfc) -> out[N,8] directly.
#define SSTRIDE 20
template<int LAYER>
__global__ __launch_bounds__(256)
void k_sage_tc(const float* __restrict__ xin,
               const float* __restrict__ Wl, const float* __restrict__ bl,
               const float* __restrict__ Wr,
               const float* __restrict__ Wfc, const float* __restrict__ bfc,
               float* __restrict__ outp, int n) {
    __shared__ unsigned As_hi[64 * SSTRIDE], As_lo[64 * SSTRIDE];
    __shared__ unsigned Bs_hi[128 * SSTRIDE], Bs_lo[128 * SSTRIDE];
    __shared__ float rowsq[64];
    __shared__ float colstat[256];
    __shared__ __align__(16) float Wfs[8 * FDIM];
    __shared__ float bfs[8];
    __shared__ float outt[64 * 9];

    const float* A2 = (LAYER == 1) ? xin : g_h;

    int t    = threadIdx.x;
    int lane = t & 31;
    int w    = t >> 5;
    int g    = lane >> 2;
    int tig  = lane & 3;
    int wr   = w >> 2;
    int wc   = w & 3;
    int row0 = blockIdx.x * 64;

    int arow = t >> 2, akv = (t * 2) & 7;
    int brow = t >> 1, bkv = (t * 4) & 7;
    int agrow = row0 + arow;
    bool aok = (agrow < n);

    if (t < 64) rowsq[t] = 0.f;
    if (LAYER == 1) colstat[t] = 0.f;
    if (LAYER == 2) {
        reinterpret_cast<float4*>(Wfs)[t] = reinterpret_cast<const float4*>(Wfc)[t];
        if (t < 8) bfs[t] = bfc[t];
        if (t < 64)
#pragma unroll
            for (int o = 0; o < 8; o++) outt[t * 9 + o] = 0.f;
    }

    float acc[2][4][4];
#pragma unroll
    for (int i = 0; i < 2; i++)
#pragma unroll
        for (int j = 0; j < 4; j++)
#pragma unroll
            for (int l = 0; l < 4; l++) acc[i][j][l] = 0.f;

    float4 pa[2], pb[4];
    {
#pragma unroll
        for (int u = 0; u < 2; u++) {
            pa[u] = make_float4(0.f, 0.f, 0.f, 0.f);
            if (aok)
                pa[u] = *reinterpret_cast<const float4*>(
                    g_agg + (size_t)agrow * FDIM + (akv + u) * 4);
        }
#pragma unroll
        for (int u = 0; u < 4; u++)
            pb[u] = *reinterpret_cast<const float4*>(
                Wl + brow * FDIM + (bkv + u) * 4);
    }

#pragma unroll 1
    for (int tt = 0; tt < 8; tt++) {
        __syncthreads();
#pragma unroll
        for (int u = 0; u < 2; u++) {
            unsigned h0, l0, h1, l1;
            split2(pa[u].x, pa[u].y, h0, l0);
            split2(pa[u].z, pa[u].w, h1, l1);
            int c0 = arow * SSTRIDE + (akv + u) * 2;
            As_hi[c0] = h0; As_hi[c0 + 1] = h1;
            As_lo[c0] = l0; As_lo[c0 + 1] = l1;
        }
#pragma unroll
        for (int u = 0; u < 4; u++) {
            unsigned h0, l0, h1, l1;
            split2(pb[u].x, pb[u].y, h0, l0);
            split2(pb[u].z, pb[u].w, h1, l1);
            int c0 = brow * SSTRIDE + (bkv + u) * 2;
            Bs_hi[c0] = h0; Bs_hi[c0 + 1] = h1;
            Bs_lo[c0] = l0; Bs_lo[c0 + 1] = l1;
        }
        __syncthreads();

        if (tt < 7) {
            int nt = tt + 1;
            const float* A = (nt & 4) ? A2 : g_agg;
            const float* W = (nt & 4) ? Wr : Wl;
            int kbase = (nt & 3) * 32;
#pragma unroll
            for (int u = 0; u < 2; u++) {
                pa[u] = make_float4(0.f, 0.f, 0.f, 0.f);
                if (aok)
                    pa[u] = *reinterpret_cast<const float4*>(
                        A + (size_t)agrow * FDIM + kbase + (akv + u) * 4);
            }
#pragma unroll
            for (int u = 0; u < 4; u++)
                pb[u] = *reinterpret_cast<const float4*>(
                    W + brow * FDIM + kbase + (bkv + u) * 4);
        }

#pragma unroll
        for (int kt = 0; kt < 2; kt++) {
            unsigned bh[4][2], bl2[4][2];
#pragma unroll
            for (int ct = 0; ct < 4; ct++) {
                int bro = (wc * 32 + ct * 8 + g) * SSTRIDE + kt * 8;
                bh[ct][0]  = Bs_hi[bro + tig];
                bh[ct][1]  = Bs_hi[bro + tig + 4];
                bl2[ct][0] = Bs_lo[bro + tig];
                bl2[ct][1] = Bs_lo[bro + tig + 4];
            }
#pragma unroll
            for (int rt = 0; rt < 2; rt++) {
                int ar0 = (wr * 32 + rt * 16 + g) * SSTRIDE + kt * 8;
                int ar1 = ar0 + 8 * SSTRIDE;
                unsigned ah[4] = {As_hi[ar0 + tig], As_hi[ar1 + tig],
                                  As_hi[ar0 + tig + 4], As_hi[ar1 + tig + 4]};
                unsigned al[4] = {As_lo[ar0 + tig], As_lo[ar1 + tig],
                                  As_lo[ar0 + tig + 4], As_lo[ar1 + tig + 4]};
#pragma unroll
                for (int ct = 0; ct < 4; ct++) {
                    mma16816(acc[rt][ct], ah, bh[ct]);
                    mma16816(acc[rt][ct], ah, bl2[ct]);
                    mma16816(acc[rt][ct], al, bh[ct]);
                }
            }
        }
    }

    // ---------- epilogue ----------
    float bias[4][2];
#pragma unroll
    for (int ct = 0; ct < 4; ct++) {
        int col = wc * 32 + ct * 8 + 2 * tig;
        bias[ct][0] = bl[col];
        bias[ct][1] = bl[col + 1];
    }
#pragma unroll
    for (int rt = 0; rt < 2; rt++)
#pragma unroll
        for (int ct = 0; ct < 4; ct++) {
            acc[rt][ct][0] += bias[ct][0];
            acc[rt][ct][1] += bias[ct][1];
            acc[rt][ct][2] += bias[ct][0];
            acc[rt][ct][3] += bias[ct][1];
        }

#pragma unroll
    for (int rt = 0; rt < 2; rt++)
#pragma unroll
        for (int h = 0; h < 2; h++) {
            float s = 0.f;
#pragma unroll
            for (int ct = 0; ct < 4; ct++) {
                float v0 = acc[rt][ct][2 * h], v1 = acc[rt][ct][2 * h + 1];
                s = fmaf(v0, v0, s);
                s = fmaf(v1, v1, s);
            }
            s += __shfl_xor_sync(0xffffffffu, s, 1);
            s += __shfl_xor_sync(0xffffffffu, s, 2);
            if (tig == 0)
                atomicAdd(&rowsq[wr * 32 + rt * 16 + g + 8 * h], s);
        }
    __syncthreads();

    float cs[4][2], cq[4][2];
#pragma unroll
    for (int ct = 0; ct < 4; ct++) {
        cs[ct][0] = cs[ct][1] = 0.f;
        cq[ct][0] = cq[ct][1] = 0.f;
    }

#pragma unroll
    for (int rt = 0; rt < 2; rt++)
#pragma unroll
        for (int h = 0; h < 2; h++) {
            int rl = wr * 32 + rt * 16 + g + 8 * h;
            int r  = row0 + rl;
            if (r >= n) continue;
            float inv = 1.0f / fmaxf(sqrtf(rowsq[rl]), 1e-12f);
            float so[8];
            if (LAYER == 2)
#pragma unroll
                for (int o = 0; o < 8; o++) so[o] = 0.f;
#pragma unroll
            for (int ct = 0; ct < 4; ct++) {
                float v0 = acc[rt][ct][2 * h] * inv;
                float v1 = acc[rt][ct][2 * h + 1] * inv;
                int col = wc * 32 + ct * 8 + 2 * tig;
                if (LAYER == 1) {
                    v0 = fmaxf(v0, 0.f);
                    v1 = fmaxf(v1, 0.f);
                    cs[ct][0] += v0; cs[ct][1] += v1;
                    cq[ct][0] = fmaf(v0, v0, cq[ct][0]);
                    cq[ct][1] = fmaf(v1, v1, cq[ct][1]);
                    *reinterpret_cast<float2*>(g_h + (size_t)r * FDIM + col) =
                        make_float2(v0, v1);
                    *reinterpret_cast<__half2*>(g_hh + (size_t)r * FDIM + col) =
                        __floats2half2_rn(v0, v1);
                } else {
#pragma unroll
                    for (int o = 0; o < 8; o++)
                        so[o] = fmaf(v0, Wfs[o * FDIM + col],
                                fmaf(v1, Wfs[o * FDIM + col + 1], so[o]));
                }
            }
            if (LAYER == 2) {
#pragma unroll
                for (int o = 0; o < 8; o++) {
                    so[o] += __shfl_xor_sync(0xffffffffu, so[o], 1);
                    so[o] += __shfl_xor_sync(0xffffffffu, so[o], 2);
                }
                if (tig == 0)
#pragma unroll
                    for (int o = 0; o < 8; o++)
                        atomicAdd(&outt[rl * 9 + o], so[o]);
            }
        }

    if (LAYER == 1) {
#pragma unroll
        for (int ct = 0; ct < 4; ct++)
#pragma unroll
            for (int j = 0; j < 2; j++) {
#pragma unroll
                for (int o = 4; o < 32; o <<= 1) {
                    cs[ct][j] += __shfl_xor_sync(0xffffffffu, cs[ct][j], o);
                    cq[ct][j] += __shfl_xor_sync(0xffffffffu, cq[ct][j], o);
                }
            }
        if (g == 0) {
#pragma unroll
            for (int ct = 0; ct < 4; ct++) {
                int col = wc * 32 + ct * 8 + 2 * tig;
                atomicAdd(&colstat[col],           cs[ct][0]);
                atomicAdd(&colstat[col + 1],       cs[ct][1]);
                atomicAdd(&colstat[128 + col],     cq[ct][0]);
                atomicAdd(&colstat[128 + col + 1], cq[ct][1]);
            }
        }
        __syncthreads();
        atomicAdd(&g_bn[t], colstat[t]);
    } else {
        __syncthreads();
        if (t < 64) {
            int r = row0 + t;
            if (r < n) {
#pragma unroll
                for (int o = 0; o < 8; o++)
                    outp[(size_t)r * 8 + o] = outt[t * 9 + o] + bfs[o];
            }
        }
    }
}

// ---------------- merged BN: coefficients + weight fold + bias ---------------
__global__ void k_bnall(const float* __restrict__ gamma,
                        const float* __restrict__ beta,
                        const float* __restrict__ W2r,
                        const float* __restrict__ b2l, float invn) {
    __shared__ float a_s[128], b_s[128], red[128];
    int t = threadIdx.x, o = blockIdx.x;
    float mu  = g_bn[t] * invn;
    float var = g_bn[128 + t] * invn - mu * mu;
    float a = gamma[t] * rsqrtf(fmaxf(var, 0.f) + 1e-5f);
    float b = fmaf(-mu, a, beta[t]);
    a_s[t] = a; b_s[t] = b;
    if (o == 0) { g_bnab[t] = a; g_bnab[128 + t] = b; }
    __syncthreads();
    float wv = W2r[o * FDIM + t];
    g_w2r[o * FDIM + t] = wv * a_s[t];
    red[t] = wv * b_s[t];
    __syncthreads();
#pragma unroll
    for (int off = 64; off; off >>= 1) {
        if (t < off) red[t] += red[t + off];
        __syncthreads();
    }
    if (t == 0) g_b2[o] = b2l[o] + red[0];
}

// ---------------- launch ------------------------------------------------------
extern "C" void kernel_launch(void* const* d_in, const int* in_sizes, int n_in,
                              void* d_out, int out_size) {
    const float* x   = (const float*)d_in[0];
    const void*  ei  = d_in[1];
    const float* W1l = (const float*)d_in[2];
    const float* b1l = (const float*)d_in[3];
    const float* W1r = (const float*)d_in[4];
    const float* gma = (const float*)d_in[5];
    const float* bta = (const float*)d_in[6];
    const float* W2l = (const float*)d_in[7];
    const float* b2l = (const float*)d_in[8];
    const float* W2r = (const float*)d_in[9];
    const float* Wfc = (const float*)d_in[10];
    const float* bfc = (const float*)d_in[11];
    float* out = (float*)d_out;

    int n  = in_sizes[0] / FDIM;
    int E  = in_sizes[1] / 2;
    int n4 = n * (FDIM / 4);
    int zb = (n + 255) / 256;
    int eb = (E + 255) / 256;
    int gb = (n + 63) / 64;
    int ab = (n * 32 + 255) / 256;
    int cb = (n4 + 255) / 256;
    int nb = (n + 1023) / 1024;

    float* w2rp; cudaGetSymbolAddress((void**)&w2rp, g_w2r);
    float* b2p;  cudaGetSymbolAddress((void**)&b2p,  g_b2);

    k_init<<<zb, 256>>>(n);
    k_hist<<<eb, 256>>>(ei, E);
    k_scanall<<<nb, 1024>>>(n, nb);
    k_permute<<<eb, 256>>>(ei, E);
    k_cvtx<<<cb, 256>>>(x, n4);
    k_agg<0><<<ab, 256>>>(n);
    k_sage_tc<1><<<gb, 256>>>(x, W1l, b1l, W1r, Wfc, bfc, out, n);
    k_bnall<<<FDIM, 128>>>(gma, bta, W2r, b2l, 1.0f / (float)n);
    k_agg<1><<<ab, 256>>>(n);
    k_sage_tc<2><<<gb, 256>>>(x, W2l, b2p, w2rp, Wfc, bfc, out, n);
}